// round 8
// baseline (speedup 1.0000x reference)
#include <cuda_runtime.h>

#define BB 32
#define NN 256
#define DD 128
#define NEG_MASK (-9000000.0f)
#define LEAK 0.2f

// Scratch for masked relation scores (allowed: __device__ globals)
__device__ float g_s1[BB * NN * NN];
__device__ float g_s2[BB * NN * NN];

// ---------------------------------------------------------------------------
// f32x2 packed-math helpers
// ---------------------------------------------------------------------------
typedef unsigned long long ull;

__device__ __forceinline__ ull fma2(ull a, ull b, ull c) {
    ull d;
    asm("fma.rn.f32x2 %0, %1, %2, %3;" : "=l"(d) : "l"(a), "l"(b), "l"(c));
    return d;
}
__device__ __forceinline__ ull pack2(float lo, float hi) {
    ull d;
    asm("mov.b64 %0, {%1, %2};" : "=l"(d) : "f"(lo), "f"(hi));
    return d;
}
__device__ __forceinline__ void unpack2(ull v, float& lo, float& hi) {
    asm("mov.b64 {%0, %1}, %2;" : "=f"(lo), "=f"(hi) : "l"(v));
}

// ---------------------------------------------------------------------------
// Kernel A: masked gated relation scores (unchanged — verified R5/R6/R7).
// ---------------------------------------------------------------------------
#define TI 8
#define P4 33
#define HIW_F4 (TI * 4 * (DD / 4))
#define HJ_F4 (128 * P4)
#define SMEM_BYTES ((HIW_F4 + HJ_F4) * 16)

extern __shared__ float4 sm4[];

__global__ __launch_bounds__(256, 2) void scores_kernel(
    const float* __restrict__ sem, const float* __restrict__ strv,
    const int* __restrict__ adj,
    const float* __restrict__ aw, const float* __restrict__ swt)
{
    const int b = blockIdx.y;
    const int i0 = blockIdx.x * TI;
    const int tid = threadIdx.x;

    float4* sm_hiw4 = sm4;
    float4* sm_hj4 = sm4 + HIW_F4;

    const int w8 = tid >> 5, lane = tid & 31;
    const int jgrp = w8 & 3, ibase = (w8 >> 2) * 4;
    const int jloc = jgrp * 32 + lane;

    for (int e = 0; e < 2; e++) {
        const float* h = e ? strv : sem;
        const float* wmat = e ? swt : aw;
        float* gs = e ? g_s2 : g_s1;

        __syncthreads();
        for (int idx = tid; idx < TI * 4 * DD; idx += 256) {
            int d = idx & 127;
            int r = (idx >> 7) & 3;
            int i = idx >> 9;
            ((float*)sm_hiw4)[(i * 128 + ((d >> 2) << 2) + r) * 4 + (d & 3)] =
                h[((b * NN) + i0 + i) * DD + d] * wmat[r * DD + d];
        }

        for (int c = 0; c < 2; c++) {
            __syncthreads();
            for (int idx = tid; idx < 128 * (DD / 4); idx += 256) {
                int d4 = idx & 31;
                int jl = idx >> 5;
                sm_hj4[jl * P4 + d4] =
                    ((const float4*)(h + ((b * NN) + c * 128 + jl) * DD))[d4];
            }
            __syncthreads();

            const int j = c * 128 + jloc;

            int msk[4], off[4];
#pragma unroll
            for (int ii = 0; ii < 4; ii++) {
                int a = adj[((b * NN) + i0 + ibase + ii) * NN + j];
                msk[ii] = a;
                int r = a > 0 ? a - 1 : 0;
                off[ii] = (ibase + ii) * 128 + r;
            }

            ull acc[4];
#pragma unroll
            for (int ii = 0; ii < 4; ii++) acc[ii] = 0ull;

            const ulonglong2* hiw2 = (const ulonglong2*)sm_hiw4;
            const ulonglong2* hj2 = (const ulonglong2*)sm_hj4 + jloc * P4;

#pragma unroll 8
            for (int d4 = 0; d4 < 32; d4++) {
                ulonglong2 hv = hj2[d4];
                int dbase = d4 << 2;
#pragma unroll
                for (int ii = 0; ii < 4; ii++) {
                    ulonglong2 wv = hiw2[off[ii] + dbase];
                    acc[ii] = fma2(wv.x, hv.x, acc[ii]);
                    acc[ii] = fma2(wv.y, hv.y, acc[ii]);
                }
            }

#pragma unroll
            for (int ii = 0; ii < 4; ii++) {
                float lo, hi;
                unpack2(acc[ii], lo, hi);
                float v = lo + hi;
                v = msk[ii] > 0 ? (v >= 0.f ? v : LEAK * v) : NEG_MASK;
                gs[((b * NN) + i0 + ibase + ii) * NN + j] = v;
            }
        }
    }
}

// ---------------------------------------------------------------------------
// Kernel B v4: register-sparse entmax. 2 rows/warp, 16-lane groups.
// Candidates compacted ONCE to smem, reloaded into per-lane registers
// (6 sem / 2 str slots, thr-padded = exact fp zeros). Bisection is pure
// register math + gsum16. Sparse GEMV over the n1 support entries.
// grid (NN/16, BB) = 512 CTAs x 256 threads.
// ---------------------------------------------------------------------------
#define CROWS2 16
#define CAP1 96
#define CAP2 32
#define NL1 (CAP1 / 16)   // 6 register slots per lane
#define NL2 (CAP2 / 16)   // 2
#define LST1 112          // float stride, %32==16 -> conflict-free dual groups
#define LST2 48

__device__ __forceinline__ float gsum16(float v) {
#pragma unroll
    for (int o = 1; o < 16; o <<= 1) v += __shfl_xor_sync(0xffffffffu, v, o);
    return v;
}
__device__ __forceinline__ float gmax16(float v) {
#pragma unroll
    for (int o = 1; o < 16; o <<= 1) v = fmaxf(v, __shfl_xor_sync(0xffffffffu, v, o));
    return v;
}

template <int MODE>
__device__ __forceinline__ float pfm(float t, float inv) {
    // t is already max(z, 0)
    if (MODE == 2) return t * t;     // alpha = 1.5
    if (MODE == 1) return t;         // alpha = 2.0
    return __powf(t, inv);           // generic
}

template <int MODE>
__device__ __forceinline__ float evalDense(const float4* __restrict__ X,
                                           float tau, float inv) {
    float a0 = 0.f, a1 = 0.f, a2 = 0.f, a3 = 0.f;
#pragma unroll
    for (int t = 0; t < 4; t++) {
        a0 += pfm<MODE>(fmaxf(X[t].x - tau, 0.f), inv);
        a1 += pfm<MODE>(fmaxf(X[t].y - tau, 0.f), inv);
        a2 += pfm<MODE>(fmaxf(X[t].z - tau, 0.f), inv);
        a3 += pfm<MODE>(fmaxf(X[t].w - tau, 0.f), inv);
    }
    return (a0 + a1) + (a2 + a3);
}

template <int MODE, int NL>
__device__ __forceinline__ float evalRegs(const float* __restrict__ L,
                                          float tau, float inv) {
    float a = 0.f;
#pragma unroll
    for (int i = 0; i < NL; i++)
        a += pfm<MODE>(fmaxf(L[i] - tau, 0.f), inv);
    return a;
}

template <int M1, int M2>
__device__ void cwork(const float* __restrict__ sem, float* __restrict__ out,
                      int b, int i0, int tid,
                      float am1_1, float am1_2, float inv1, float inv2,
                      float* sV1, unsigned char* sI1, float* sV2,
                      float (*sDWF)[NN], int* sN1, float* sScale)
{
    const int w = tid >> 5, lane = tid & 31;
    const int g = lane >> 4, s = lane & 15;
    const int r = 2 * w + g;
    const int row = i0 + r;

    float* sList1 = sV1 + r * LST1;
    unsigned char* sIdx1 = sI1 + r * LST1;
    float* sList2 = sV2 + r * LST2;

    const float4* x1g = (const float4*)(g_s1 + ((b * NN) + row) * NN);
    const float4* x2g = (const float4*)(g_s2 + ((b * NN) + row) * NN);

    // Load + scale (FMUL.RN as reference)
    float4 X1[4], X2[4];
    float mx1 = -3.4e38f, mx2 = -3.4e38f;
#pragma unroll
    for (int t = 0; t < 4; t++) {
        float4 v = x1g[s + 16 * t];
        v.x *= am1_1; v.y *= am1_1; v.z *= am1_1; v.w *= am1_1;
        X1[t] = v;
        mx1 = fmaxf(mx1, fmaxf(fmaxf(v.x, v.y), fmaxf(v.z, v.w)));
        float4 u = x2g[s + 16 * t];
        u.x *= am1_2; u.y *= am1_2; u.z *= am1_2; u.w *= am1_2;
        X2[t] = u;
        mx2 = fmaxf(mx2, fmaxf(fmaxf(u.x, u.y), fmaxf(u.z, u.w)));
    }
    mx1 = gmax16(mx1);
    mx2 = gmax16(mx2);
    const float thr1 = mx1 - 1.f, thr2 = mx2 - 1.f;   // tau_lo

    // Candidate counts + one packed 16-lane inclusive scan (R7-verified)
    int c1 = 0, c2 = 0;
#pragma unroll
    for (int t = 0; t < 4; t++) {
        c1 += (X1[t].x > thr1) + (X1[t].y > thr1) + (X1[t].z > thr1) + (X1[t].w > thr1);
        c2 += (X2[t].x > thr2) + (X2[t].y > thr2) + (X2[t].z > thr2) + (X2[t].w > thr2);
    }
    int incl = c1 | (c2 << 16);
#pragma unroll
    for (int o = 1; o < 16; o <<= 1) {
        int u = __shfl_up_sync(0xffffffffu, incl, o);
        if (s >= o) incl += u;
    }
    int tot = __shfl_sync(0xffffffffu, incl, (lane & 16) | 15);
    const int ntot1 = tot & 0xffff, ntot2 = tot >> 16;
    const int pfx1 = (incl & 0xffff) - c1, pfx2 = (incl >> 16) - c2;

    const bool ok1 = (M1 != 0) && (ntot1 <= CAP1);
    const bool ok2 = (M2 != 0) && (ntot2 <= CAP2);

    // Compact to smem (once), pad to cap with thr (exact zeros for tau>=thr)
    if (ok1) {
        int pos = pfx1;
#pragma unroll
        for (int t = 0; t < 4; t++) {
            int jb = 4 * (s + 16 * t);
            if (X1[t].x > thr1) { sList1[pos] = X1[t].x; sIdx1[pos] = (unsigned char)jb;       pos++; }
            if (X1[t].y > thr1) { sList1[pos] = X1[t].y; sIdx1[pos] = (unsigned char)(jb + 1); pos++; }
            if (X1[t].z > thr1) { sList1[pos] = X1[t].z; sIdx1[pos] = (unsigned char)(jb + 2); pos++; }
            if (X1[t].w > thr1) { sList1[pos] = X1[t].w; sIdx1[pos] = (unsigned char)(jb + 3); pos++; }
        }
        for (int p = ntot1 + s; p < CAP1; p += 16) { sList1[p] = thr1; sIdx1[p] = 0; }
    }
    if (ok2) {
        int pos = pfx2;
#pragma unroll
        for (int t = 0; t < 4; t++) {
            if (X2[t].x > thr2) sList2[pos++] = X2[t].x;
            if (X2[t].y > thr2) sList2[pos++] = X2[t].y;
            if (X2[t].z > thr2) sList2[pos++] = X2[t].z;
            if (X2[t].w > thr2) sList2[pos++] = X2[t].w;
        }
        for (int p = ntot2 + s; p < CAP2; p += 16) sList2[p] = thr2;
    }
    __syncwarp();

    // Reload candidates into per-lane registers (once, static unroll)
    float L1[NL1];
    int I1[NL1];
    float L2[NL2];
    if (ok1) {
#pragma unroll
        for (int i = 0; i < NL1; i++) {
            L1[i] = sList1[s + 16 * i];
            I1[i] = sIdx1[s + 16 * i];
        }
    }
    if (ok2) {
#pragma unroll
        for (int i = 0; i < NL2; i++) L2[i] = sList2[s + 16 * i];
    }

    // 30-iteration bisection (reference-faithful), pure register eval
    float tau1 = thr1, tau2 = thr2;
    float dm1 = 1.f - exp2f(-8.f * am1_1);
    float dm2 = 1.f - exp2f(-8.f * am1_2);

    float f1 = ok1 ? evalRegs<M1, NL1>(L1, tau1, inv1) : evalDense<M1>(X1, tau1, inv1);
    float f2 = ok2 ? evalRegs<M2, NL2>(L2, tau2, inv2) : evalDense<M2>(X2, tau2, inv2);
    const float flo1 = gsum16(f1) - 1.f;
    const float flo2 = gsum16(f2) - 1.f;

#pragma unroll 1
    for (int it = 0; it < 30; it++) {
        dm1 *= 0.5f;
        dm2 *= 0.5f;
        float tm1 = tau1 + dm1, tm2 = tau2 + dm2;
        float a = ok1 ? evalRegs<M1, NL1>(L1, tm1, inv1) : evalDense<M1>(X1, tm1, inv1);
        float bs = ok2 ? evalRegs<M2, NL2>(L2, tm2, inv2) : evalDense<M2>(X2, tm2, inv2);
        a = gsum16(a);
        bs = gsum16(bs);
        if ((a - 1.f) * flo1 >= 0.f) tau1 = tm1;
        if ((bs - 1.f) * flo2 >= 0.f) tau2 = tm2;
    }

    const float S1 = gsum16(ok1 ? evalRegs<M1, NL1>(L1, tau1, inv1)
                                : evalDense<M1>(X1, tau1, inv1));
    const float S2 = gsum16(ok2 ? evalRegs<M2, NL2>(L2, tau2, inv2)
                                : evalDense<M2>(X2, tau2, inv2));

    // wf = p1*p2 (support within list1); p2 recomputed from g_s2 (R6-verified)
    float s3p = 0.f;
    if (ok1) {
        const float* g2row = g_s2 + ((b * NN) + row) * NN;
#pragma unroll
        for (int i = 0; i < NL1; i++) {
            float p1 = pfm<M1>(fmaxf(L1[i] - tau1, 0.f), inv1);
            float x2 = __fmul_rn(g2row[I1[i]], am1_2);
            float p2 = pfm<M2>(fmaxf(x2 - tau2, 0.f), inv2);
            float wf = p1 * p2;
            s3p += wf;
            sList1[s + 16 * i] = wf;   // overwrite value slot with wf
        }
    } else {
#pragma unroll
        for (int t = 0; t < 4; t++) {
            int jb = 4 * (s + 16 * t);
            float w0 = pfm<M1>(fmaxf(X1[t].x - tau1, 0.f), inv1) * pfm<M2>(fmaxf(X2[t].x - tau2, 0.f), inv2);
            float w1 = pfm<M1>(fmaxf(X1[t].y - tau1, 0.f), inv1) * pfm<M2>(fmaxf(X2[t].y - tau2, 0.f), inv2);
            float w2 = pfm<M1>(fmaxf(X1[t].z - tau1, 0.f), inv1) * pfm<M2>(fmaxf(X2[t].z - tau2, 0.f), inv2);
            float w3 = pfm<M1>(fmaxf(X1[t].w - tau1, 0.f), inv1) * pfm<M2>(fmaxf(X2[t].w - tau2, 0.f), inv2);
            *(float4*)&sDWF[r][jb] = make_float4(w0, w1, w2, w3);
            s3p += (w0 + w1) + (w2 + w3);
        }
    }
    float s3 = gsum16(s3p);
    if (s == 0) {
        sN1[r] = ok1 ? ntot1 : -1;
        // weight = p1p2/(S1S2) / (S3/(S1S2)+1e-7) = p1p2 / (S3 + 1e-7 S1 S2)
        sScale[r] = 1.f / (s3 + 1e-7f * S1 * S2);
    }
    __syncwarp();

    // Sparse output GEMV: warp-wide per row, lane = d4; wf/idx broadcast reads
    const ulonglong2* semb2 = (const ulonglong2*)(sem + b * NN * DD);
#pragma unroll
    for (int q = 0; q < 2; q++) {
        int rr = 2 * w + q;
        int n1 = sN1[rr];
        float sc = sScale[rr];
        const float* wfl = sV1 + rr * LST1;
        const unsigned char* jl = sI1 + rr * LST1;
        ull accA = 0ull, accB = 0ull;
        if (n1 >= 0) {
#pragma unroll 1
            for (int k = 0; k < n1; k++) {
                float wf = wfl[k];
                int j = jl[k];
                ulonglong2 vv = semb2[j * 32 + lane];
                ull wv = pack2(wf, wf);
                accA = fma2(wv, vv.x, accA);
                accB = fma2(wv, vv.y, accB);
            }
        } else {
#pragma unroll 1
            for (int j = 0; j < NN; j++) {
                float wf = sDWF[rr][j];
                ulonglong2 vv = semb2[j * 32 + lane];
                ull wv = pack2(wf, wf);
                accA = fma2(wv, vv.x, accA);
                accB = fma2(wv, vv.y, accB);
            }
        }
        float4 o;
        unpack2(accA, o.x, o.y);
        unpack2(accB, o.z, o.w);
        o.x *= sc; o.y *= sc; o.z *= sc; o.w *= sc;
        ((float4*)out)[((b * NN) + i0 + rr) * 32 + lane] = o;
    }
}

__global__ __launch_bounds__(256, 3) void combine4_kernel(
    const float* __restrict__ sem,
    const float* __restrict__ alpha1p, const float* __restrict__ alpha2p,
    float* __restrict__ out)
{
    __shared__ float sV1[CROWS2 * LST1];
    __shared__ unsigned char sI1[CROWS2 * LST1];
    __shared__ float sV2[CROWS2 * LST2];
    __shared__ float sDWF[CROWS2][NN];
    __shared__ int sN1[CROWS2];
    __shared__ float sScale[CROWS2];

    const int b = blockIdx.y, i0 = blockIdx.x * CROWS2;
    const int tid = threadIdx.x;

    float a1 = alpha1p[0], a2 = alpha2p[0];
    float am1_1 = a1 - 1.f, am1_2 = a2 - 1.f;
    float inv1 = 1.f / am1_1, inv2 = 1.f / am1_2;
    int m1 = (fabsf(a1 - 1.5f) < 1e-4f) ? 2 : ((fabsf(a1 - 2.f) < 1e-4f) ? 1 : 0);
    int m2 = (fabsf(a2 - 1.5f) < 1e-4f) ? 2 : ((fabsf(a2 - 2.f) < 1e-4f) ? 1 : 0);

    if (m1 == 2 && m2 == 1)
        cwork<2, 1>(sem, out, b, i0, tid, am1_1, am1_2, inv1, inv2,
                    sV1, sI1, sV2, sDWF, sN1, sScale);
    else if (m1 == 1 && m2 == 2)
        cwork<1, 2>(sem, out, b, i0, tid, am1_1, am1_2, inv1, inv2,
                    sV1, sI1, sV2, sDWF, sN1, sScale);
    else if (m1 == 2 && m2 == 2)
        cwork<2, 2>(sem, out, b, i0, tid, am1_1, am1_2, inv1, inv2,
                    sV1, sI1, sV2, sDWF, sN1, sScale);
    else if (m1 == 1 && m2 == 1)
        cwork<1, 1>(sem, out, b, i0, tid, am1_1, am1_2, inv1, inv2,
                    sV1, sI1, sV2, sDWF, sN1, sScale);
    else
        cwork<0, 0>(sem, out, b, i0, tid, am1_1, am1_2, inv1, inv2,
                    sV1, sI1, sV2, sDWF, sN1, sScale);
}

// ---------------------------------------------------------------------------
extern "C" void kernel_launch(void* const* d_in, const int* in_sizes, int n_in,
                              void* d_out, int out_size)
{
    const float* sem  = (const float*)d_in[0];
    const float* strv = (const float*)d_in[1];
    const int*   adj  = (const int*)d_in[2];
    const float* aw   = (const float*)d_in[3];
    const float* swt  = (const float*)d_in[4];
    const float* a1   = (const float*)d_in[5];
    const float* a2   = (const float*)d_in[6];
    float* out = (float*)d_out;

    cudaFuncSetAttribute(scores_kernel,
                         cudaFuncAttributeMaxDynamicSharedMemorySize, SMEM_BYTES);

    scores_kernel<<<dim3(NN / TI, BB), 256, SMEM_BYTES>>>(
        sem, strv, adj, aw, swt);
    combine4_kernel<<<dim3(NN / CROWS2, BB), 256>>>(sem, a1, a2, out);
}